// round 3
// baseline (speedup 1.0000x reference)
#include <cuda_runtime.h>
#include <cstdint>
#include <cstddef>

// ---------------- problem constants ----------------
#define B_TOTAL   32768            // N*T = 64*512
#define VN        10
#define C         128
#define NB        8                // batch items per block
#define M_ROWS    80               // NB*VN
#define GRID_FUSED (B_TOTAL / NB)  // 4096
#define THREADS_FUSED 320          // 10 warps: (mtile 0..4) x (nhalf 0..1)
#define STATS_BLOCKS 296
#define N4_TOTAL  10485760         // 64*512*10*128/4
#define CNT_INV   (1.0f / 327680.0f)
#define BN_EPS    1e-5f

// ---------------- smem layout (floats) ----------------
#define XS_STRIDE 132
#define QS_STRIDE 386
#define WS_STRIDE 72
#define XS_OFF    0
#define QS_OFF    (M_ROWS * XS_STRIDE)                 // 10560
#define WS_OFF    (QS_OFF + M_ROWS * QS_STRIDE)        // 10560 + 30880
#define MK_OFF    (WS_OFF + 128 * WS_STRIDE)           // + 9216
#define SMEM_FLOATS (MK_OFF + 100)
#define SMEM_BYTES  (SMEM_FLOATS * 4)                  // 203024 B < 227 KB

// ---------------- device scratch (no allocation allowed) ----------------
__device__ float g_part[STATS_BLOCKS * 256];   // per-block partial sums / sumsq
__device__ float g_wqkv[128 * 384];            // tf32-rounded s-scaled qkv weights
__device__ float g_tw[384];                    // t @ w_qkv  (fp32 exact)
__device__ float g_wout[128 * 128];            // tf32-rounded output proj weights

// ---------------- helpers ----------------
__device__ __forceinline__ uint32_t f2tf32(float x) {
    uint32_t u;
    asm("cvt.rna.tf32.f32 %0, %1;" : "=r"(u) : "f"(x));
    return u;
}

__device__ __forceinline__ void mma8(float* c, const uint32_t* a, uint32_t b0, uint32_t b1) {
    asm volatile(
        "mma.sync.aligned.m16n8k8.row.col.f32.tf32.tf32.f32 "
        "{%0,%1,%2,%3}, {%4,%5,%6,%7}, {%8,%9}, {%0,%1,%2,%3};\n"
        : "+f"(c[0]), "+f"(c[1]), "+f"(c[2]), "+f"(c[3])
        : "r"(a[0]), "r"(a[1]), "r"(a[2]), "r"(a[3]), "r"(b0), "r"(b1));
}

// ================= kernel 1: BN statistics (deterministic) =================
__global__ void __launch_bounds__(256) k_stats(const float4* __restrict__ x) {
    float sx = 0.f, sy = 0.f, sz = 0.f, sw = 0.f;
    float qx = 0.f, qy = 0.f, qz = 0.f, qw = 0.f;
    const int stride = STATS_BLOCKS * 256;   // multiple of 32 -> fixed channel quad per thread
    for (int i = blockIdx.x * 256 + threadIdx.x; i < N4_TOTAL; i += stride) {
        float4 v = x[i];
        sx += v.x; sy += v.y; sz += v.z; sw += v.w;
        qx += v.x * v.x; qy += v.y * v.y; qz += v.z * v.z; qw += v.w * v.w;
    }
    __shared__ float sh[4096];   // [0:2048) sums, [2048:4096) sumsq; 8 warps x 128ch
    int w = threadIdx.x >> 5, l = threadIdx.x & 31;
    sh[w * 128 + l * 4 + 0] = sx; sh[w * 128 + l * 4 + 1] = sy;
    sh[w * 128 + l * 4 + 2] = sz; sh[w * 128 + l * 4 + 3] = sw;
    sh[2048 + w * 128 + l * 4 + 0] = qx; sh[2048 + w * 128 + l * 4 + 1] = qy;
    sh[2048 + w * 128 + l * 4 + 2] = qz; sh[2048 + w * 128 + l * 4 + 3] = qw;
    __syncthreads();
    int t = threadIdx.x;
    if (t < 128) {
        float a = 0.f;
        #pragma unroll
        for (int ww = 0; ww < 8; ++ww) a += sh[ww * 128 + t];
        g_part[blockIdx.x * 256 + t] = a;
    } else if (t < 256) {
        int u = t - 128;
        float a = 0.f;
        #pragma unroll
        for (int ww = 0; ww < 8; ++ww) a += sh[2048 + ww * 128 + u];
        g_part[blockIdx.x * 256 + t] = a;
    }
}

// ================= kernel 2: fold BN into weights =================
__global__ void __launch_bounds__(384) k_prep(
    const float* __restrict__ gamma, const float* __restrict__ beta,
    const float* __restrict__ wqkv, const float* __restrict__ wout)
{
    __shared__ float s_sum[256];
    __shared__ float s_s[128], s_t[128];
    int t = threadIdx.x;
    if (t < 256) {
        float a = 0.f;
        for (int b = 0; b < STATS_BLOCKS; ++b) a += g_part[b * 256 + t];
        s_sum[t] = a;
    }
    __syncthreads();
    if (t < 128) {
        float mean = s_sum[t] * CNT_INV;
        float var  = s_sum[128 + t] * CNT_INV - mean * mean;
        float rstd = 1.0f / sqrtf(var + BN_EPS);
        float sc = gamma[t] * rstd;
        s_s[t] = sc;
        s_t[t] = beta[t] - mean * sc;
    }
    __syncthreads();
    // W' = diag(s) * w_qkv  (tf32-rounded); t stride = 384 so n = t, k = iter
    for (int k = 0; k < 128; ++k)
        g_wqkv[k * 384 + t] = __uint_as_float(f2tf32(s_s[k] * wqkv[k * 384 + t]));
    // tW = t @ w_qkv (fp32 exact)
    {
        float a = 0.f;
        for (int k = 0; k < 128; ++k) a += s_t[k] * wqkv[k * 384 + t];
        g_tw[t] = a;
    }
    for (int i = t; i < 16384; i += 384)
        g_wout[i] = __uint_as_float(f2tf32(wout[i]));
}

// ================= kernel 3: fused qkv GEMM + attention + out-proj =================
__global__ void __launch_bounds__(THREADS_FUSED, 1) k_fused(
    const float* __restrict__ x, const float* __restrict__ b_out,
    const float* __restrict__ mask, float* __restrict__ out)
{
    extern __shared__ float sm[];
    float* Xs = sm + XS_OFF;   // X tile (tf32), later reused as attention output O
    float* Qs = sm + QS_OFF;   // qkv fp32, 80 x 386
    float* Ws = sm + WS_OFF;   // weight chunk 128 x 72
    float* Mk = sm + MK_OFF;   // 10x10 mask

    const int tid = threadIdx.x;
    const int warp = tid >> 5, lane = tid & 31;
    const int g = lane >> 2, tq = lane & 3;
    const int blk = blockIdx.x;

    // ---- P0: stage X tile (tf32-rounded), fully coalesced ----
    const float4* xg = (const float4*)(x + (size_t)blk * (NB * VN * C));
    #pragma unroll
    for (int it = 0; it < 8; ++it) {
        int idx = tid + it * THREADS_FUSED;      // 0..2559 exact
        int row = idx >> 5, c4 = idx & 31;
        float4 v = xg[idx];
        float4 o;
        o.x = __uint_as_float(f2tf32(v.x));
        o.y = __uint_as_float(f2tf32(v.y));
        o.z = __uint_as_float(f2tf32(v.z));
        o.w = __uint_as_float(f2tf32(v.w));
        *(float4*)&Xs[row * XS_STRIDE + c4 * 4] = o;
    }
    if (tid < 100) Mk[tid] = mask[tid];
    __syncthreads();

    const int mt = warp >> 1;     // m-tile (0..4)
    const int nh = warp & 1;      // n-half of the 64-wide chunk
    const int r0 = mt * 16 + g;

    // ---- preload A fragments for the whole K=128 into registers ----
    uint32_t a[16][4];
    #pragma unroll
    for (int kk = 0; kk < 16; ++kk) {
        int kb = kk * 8;
        a[kk][0] = __float_as_uint(Xs[r0 * XS_STRIDE + kb + tq]);
        a[kk][1] = __float_as_uint(Xs[(r0 + 8) * XS_STRIDE + kb + tq]);
        a[kk][2] = __float_as_uint(Xs[r0 * XS_STRIDE + kb + tq + 4]);
        a[kk][3] = __float_as_uint(Xs[(r0 + 8) * XS_STRIDE + kb + tq + 4]);
    }

    // ---- P1: qkv = X @ W' + tW, N streamed in 6 chunks of 64 ----
    for (int ch = 0; ch < 6; ++ch) {
        for (int i = tid; i < 8192; i += THREADS_FUSED) {
            int k = i >> 6, n = i & 63;
            Ws[k * WS_STRIDE + n] = g_wqkv[k * 384 + ch * 64 + n];
        }
        __syncthreads();
        float acc[4][4];
        #pragma unroll
        for (int nt = 0; nt < 4; ++nt)
            #pragma unroll
            for (int j = 0; j < 4; ++j) acc[nt][j] = 0.f;
        #pragma unroll
        for (int kk = 0; kk < 16; ++kk) {
            int krow = kk * 8;
            #pragma unroll
            for (int nt = 0; nt < 4; ++nt) {
                int nc = nh * 32 + nt * 8 + g;
                uint32_t b0 = __float_as_uint(Ws[(krow + tq) * WS_STRIDE + nc]);
                uint32_t b1 = __float_as_uint(Ws[(krow + tq + 4) * WS_STRIDE + nc]);
                mma8(acc[nt], a[kk], b0, b1);
            }
        }
        #pragma unroll
        for (int nt = 0; nt < 4; ++nt) {
            int col = ch * 64 + nh * 32 + nt * 8 + 2 * tq;
            float t0 = g_tw[col], t1 = g_tw[col + 1];
            *(float2*)&Qs[r0 * QS_STRIDE + col] =
                make_float2(acc[nt][0] + t0, acc[nt][1] + t1);
            *(float2*)&Qs[(r0 + 8) * QS_STRIDE + col] =
                make_float2(acc[nt][2] + t0, acc[nt][3] + t1);
        }
        __syncthreads();
    }

    // ---- P2: per-(batch,head) masked softmax attention, scalar fp32 ----
    {
        int half = lane >> 4;      // 2 pairs per warp iteration
        int i = lane & 15;         // row within the 10-token group
        #pragma unroll
        for (int it = 0; it < 4; ++it) {
            int p = it * 20 + warp * 2 + half;   // (batch_in_block, head) pair id
            if (p < 64 && i < VN) {
                int b = p >> 3, h = p & 7;
                const float* qr = &Qs[(b * VN + i) * QS_STRIDE + h * 16];
                float q[16];
                #pragma unroll
                for (int d = 0; d < 16; ++d) q[d] = qr[d];
                float e[10]; float ssum = 0.f;
                #pragma unroll
                for (int j = 0; j < VN; ++j) {
                    const float* kr = &Qs[(b * VN + j) * QS_STRIDE + 128 + h * 16];
                    float dot = 0.f;
                    #pragma unroll
                    for (int d = 0; d < 16; ++d) dot += q[d] * kr[d];
                    float z = dot * 0.25f * Mk[i * VN + j];   // scale=DH^-0.5, mult. mask
                    e[j] = __expf(z);
                    ssum += e[j];
                }
                float o[16];
                #pragma unroll
                for (int d = 0; d < 16; ++d) o[d] = 0.f;
                #pragma unroll
                for (int j = 0; j < VN; ++j) {
                    const float* vr = &Qs[(b * VN + j) * QS_STRIDE + 256 + h * 16];
                    float wj = e[j];
                    #pragma unroll
                    for (int d = 0; d < 16; ++d) o[d] += wj * vr[d];
                }
                float inv = 1.0f / ssum;
                #pragma unroll
                for (int d = 0; d < 16; ++d)
                    Xs[(b * VN + i) * XS_STRIDE + h * 16 + d] =
                        __uint_as_float(f2tf32(o[d] * inv));
            }
        }
    }
    __syncthreads();

    // ---- P3: out = O @ w_out + b_out ----
    #pragma unroll
    for (int kk = 0; kk < 16; ++kk) {
        int kb = kk * 8;
        a[kk][0] = __float_as_uint(Xs[r0 * XS_STRIDE + kb + tq]);
        a[kk][1] = __float_as_uint(Xs[(r0 + 8) * XS_STRIDE + kb + tq]);
        a[kk][2] = __float_as_uint(Xs[r0 * XS_STRIDE + kb + tq + 4]);
        a[kk][3] = __float_as_uint(Xs[(r0 + 8) * XS_STRIDE + kb + tq + 4]);
    }
    for (int ch = 0; ch < 2; ++ch) {
        for (int i = tid; i < 8192; i += THREADS_FUSED) {
            int k = i >> 6, n = i & 63;
            Ws[k * WS_STRIDE + n] = g_wout[k * 128 + ch * 64 + n];
        }
        __syncthreads();
        float acc[4][4];
        #pragma unroll
        for (int nt = 0; nt < 4; ++nt)
            #pragma unroll
            for (int j = 0; j < 4; ++j) acc[nt][j] = 0.f;
        #pragma unroll
        for (int kk = 0; kk < 16; ++kk) {
            int krow = kk * 8;
            #pragma unroll
            for (int nt = 0; nt < 4; ++nt) {
                int nc = nh * 32 + nt * 8 + g;
                uint32_t b0 = __float_as_uint(Ws[(krow + tq) * WS_STRIDE + nc]);
                uint32_t b1 = __float_as_uint(Ws[(krow + tq + 4) * WS_STRIDE + nc]);
                mma8(acc[nt], a[kk], b0, b1);
            }
        }
        #pragma unroll
        for (int nt = 0; nt < 4; ++nt) {
            int col = ch * 64 + nh * 32 + nt * 8 + 2 * tq;
            float b0v = b_out[col], b1v = b_out[col + 1];
            size_t ro = ((size_t)blk * M_ROWS + r0) * C + col;
            *(float2*)&out[ro] = make_float2(acc[nt][0] + b0v, acc[nt][1] + b1v);
            *(float2*)&out[ro + 8 * C] = make_float2(acc[nt][2] + b0v, acc[nt][3] + b1v);
        }
        __syncthreads();
    }
}

// ================= launch =================
extern "C" void kernel_launch(void* const* d_in, const int* in_sizes, int n_in,
                              void* d_out, int out_size) {
    const float* x     = (const float*)d_in[0];
    const float* gamma = (const float*)d_in[1];
    const float* beta  = (const float*)d_in[2];
    const float* wqkv  = (const float*)d_in[3];
    const float* wout  = (const float*)d_in[4];
    const float* bout  = (const float*)d_in[5];
    const float* mask  = (const float*)d_in[6];

    cudaFuncSetAttribute(k_fused, cudaFuncAttributeMaxDynamicSharedMemorySize, SMEM_BYTES);

    k_stats<<<STATS_BLOCKS, 256>>>((const float4*)x);
    k_prep<<<1, 384>>>(gamma, beta, wqkv, wout);
    k_fused<<<GRID_FUSED, THREADS_FUSED, SMEM_BYTES>>>(x, bout, mask, (float*)d_out);
}

// round 5
// speedup vs baseline: 1.0566x; 1.0566x over previous
#include <cuda_runtime.h>
#include <cstdint>
#include <cstddef>

// ---------------- problem constants ----------------
#define B_TOTAL   32768            // N*T = 64*512
#define VN        10
#define C         128
#define NB        8                // batch items per block
#define M_ROWS    80               // NB*VN
#define GRID_FUSED (B_TOTAL / NB)  // 4096
#define THREADS_FUSED 320          // 10 warps: (mtile 0..4) x (nhalf 0..1)
#define STATS_BLOCKS 592
#define N4_TOTAL  10485760         // 64*512*10*128/4
#define CNT_INV   (1.0f / 327680.0f)
#define BN_EPS    1e-5f

// ---------------- smem layout (floats) ----------------
#define XS_STRIDE 132
#define QS_STRIDE 388              // divisible by 4 -> float4-aligned rows
#define WS_STRIDE 72
#define XS_OFF    0
#define QS_OFF    (M_ROWS * XS_STRIDE)                 // 10560
#define WS_OFF    (QS_OFF + M_ROWS * QS_STRIDE)        // + 31040
#define MK_OFF    (WS_OFF + 128 * WS_STRIDE)           // + 9216
#define SMEM_FLOATS (MK_OFF + 100)
#define SMEM_BYTES  (SMEM_FLOATS * 4)                  // 203664 B < 227 KB

// ---------------- device scratch (no allocation allowed) ----------------
__device__ float g_part[STATS_BLOCKS * 256];   // per-block partial sums / sumsq
__device__ float g_wqkv[128 * 384];            // tf32-rounded s-scaled qkv weights
__device__ float g_tw[384];                    // t @ w_qkv  (fp32 exact)
__device__ float g_wout[128 * 128];            // tf32-rounded output proj weights

// ---------------- helpers ----------------
__device__ __forceinline__ uint32_t f2tf32(float x) {
    uint32_t u;
    asm("cvt.rna.tf32.f32 %0, %1;" : "=r"(u) : "f"(x));
    return u;
}

__device__ __forceinline__ void mma8(float* c, const uint32_t* a, uint32_t b0, uint32_t b1) {
    asm volatile(
        "mma.sync.aligned.m16n8k8.row.col.f32.tf32.tf32.f32 "
        "{%0,%1,%2,%3}, {%4,%5,%6,%7}, {%8,%9}, {%0,%1,%2,%3};\n"
        : "+f"(c[0]), "+f"(c[1]), "+f"(c[2]), "+f"(c[3])
        : "r"(a[0]), "r"(a[1]), "r"(a[2]), "r"(a[3]), "r"(b0), "r"(b1));
}

// ================= kernel 1: BN statistics (deterministic) =================
__global__ void __launch_bounds__(256) k_stats(const float4* __restrict__ x) {
    float sx = 0.f, sy = 0.f, sz = 0.f, sw = 0.f;
    float qx = 0.f, qy = 0.f, qz = 0.f, qw = 0.f;
    const int stride = STATS_BLOCKS * 256;   // multiple of 32 -> fixed channel quad per thread
    for (int i = blockIdx.x * 256 + threadIdx.x; i < N4_TOTAL; i += stride) {
        float4 v = x[i];
        sx += v.x; sy += v.y; sz += v.z; sw += v.w;
        qx += v.x * v.x; qy += v.y * v.y; qz += v.z * v.z; qw += v.w * v.w;
    }
    __shared__ float sh[4096];   // [0:2048) sums, [2048:4096) sumsq; 8 warps x 128ch
    int w = threadIdx.x >> 5, l = threadIdx.x & 31;
    sh[w * 128 + l * 4 + 0] = sx; sh[w * 128 + l * 4 + 1] = sy;
    sh[w * 128 + l * 4 + 2] = sz; sh[w * 128 + l * 4 + 3] = sw;
    sh[2048 + w * 128 + l * 4 + 0] = qx; sh[2048 + w * 128 + l * 4 + 1] = qy;
    sh[2048 + w * 128 + l * 4 + 2] = qz; sh[2048 + w * 128 + l * 4 + 3] = qw;
    __syncthreads();
    int t = threadIdx.x;
    if (t < 128) {
        float a = 0.f;
        #pragma unroll
        for (int ww = 0; ww < 8; ++ww) a += sh[ww * 128 + t];
        g_part[blockIdx.x * 256 + t] = a;
    } else if (t < 256) {
        int u = t - 128;
        float a = 0.f;
        #pragma unroll
        for (int ww = 0; ww < 8; ++ww) a += sh[2048 + ww * 128 + u];
        g_part[blockIdx.x * 256 + t] = a;
    }
}

// ================= kernel 2: fold BN into weights =================
__global__ void __launch_bounds__(384) k_prep(
    const float* __restrict__ gamma, const float* __restrict__ beta,
    const float* __restrict__ wqkv, const float* __restrict__ wout)
{
    __shared__ float s_sum[256];
    __shared__ float s_s[128], s_t[128];
    int t = threadIdx.x;
    if (t < 256) {
        float a = 0.f;
        for (int b = 0; b < STATS_BLOCKS; ++b) a += g_part[b * 256 + t];
        s_sum[t] = a;
    }
    __syncthreads();
    if (t < 128) {
        float mean = s_sum[t] * CNT_INV;
        float var  = s_sum[128 + t] * CNT_INV - mean * mean;
        float rstd = 1.0f / sqrtf(var + BN_EPS);
        float sc = gamma[t] * rstd;
        s_s[t] = sc;
        s_t[t] = beta[t] - mean * sc;
    }
    __syncthreads();
    // W' = diag(s) * w_qkv  (tf32-rounded); t stride = 384 so n = t, k = iter
    for (int k = 0; k < 128; ++k)
        g_wqkv[k * 384 + t] = __uint_as_float(f2tf32(s_s[k] * wqkv[k * 384 + t]));
    // tW = t @ w_qkv (fp32 exact)
    {
        float a = 0.f;
        for (int k = 0; k < 128; ++k) a += s_t[k] * wqkv[k * 384 + t];
        g_tw[t] = a;
    }
    for (int i = t; i < 16384; i += 384)
        g_wout[i] = __uint_as_float(f2tf32(wout[i]));
}

// ================= kernel 3: fused qkv GEMM + attention + out-proj =================
__global__ void __launch_bounds__(THREADS_FUSED, 1) k_fused(
    const float* __restrict__ x, const float* __restrict__ b_out,
    const float* __restrict__ mask, float* __restrict__ out)
{
    extern __shared__ float sm[];
    float* Xs = sm + XS_OFF;   // X tile (tf32), later reused as attention output O
    float* Qs = sm + QS_OFF;   // qkv fp32, 80 x 388
    float* Ws = sm + WS_OFF;   // weight chunk 128 x 72
    float* Mk = sm + MK_OFF;   // 10x10 mask

    const int tid = threadIdx.x;
    const int warp = tid >> 5, lane = tid & 31;
    const int g = lane >> 2, tq = lane & 3;
    const int blk = blockIdx.x;

    // ---- P0: stage X tile (tf32-rounded), fully coalesced ----
    const float4* xg = (const float4*)(x + (size_t)blk * (NB * VN * C));
    #pragma unroll
    for (int it = 0; it < 8; ++it) {
        int idx = tid + it * THREADS_FUSED;      // 0..2559 exact
        int row = idx >> 5, c4 = idx & 31;
        float4 v = xg[idx];
        float4 o;
        o.x = __uint_as_float(f2tf32(v.x));
        o.y = __uint_as_float(f2tf32(v.y));
        o.z = __uint_as_float(f2tf32(v.z));
        o.w = __uint_as_float(f2tf32(v.w));
        *(float4*)&Xs[row * XS_STRIDE + c4 * 4] = o;
    }
    if (tid < 100) Mk[tid] = mask[tid];
    __syncthreads();

    const int mt = warp >> 1;     // m-tile (0..4)
    const int nh = warp & 1;      // n-half of the 64-wide chunk
    const int r0 = mt * 16 + g;

    // ---- preload A fragments for the whole K=128 into registers ----
    uint32_t a[16][4];
    #pragma unroll
    for (int kk = 0; kk < 16; ++kk) {
        int kb = kk * 8;
        a[kk][0] = __float_as_uint(Xs[r0 * XS_STRIDE + kb + tq]);
        a[kk][1] = __float_as_uint(Xs[(r0 + 8) * XS_STRIDE + kb + tq]);
        a[kk][2] = __float_as_uint(Xs[r0 * XS_STRIDE + kb + tq + 4]);
        a[kk][3] = __float_as_uint(Xs[(r0 + 8) * XS_STRIDE + kb + tq + 4]);
    }

    // ---- P1: qkv = X @ W' + tW, N streamed in 6 chunks of 64 ----
    for (int ch = 0; ch < 6; ++ch) {
        // float4-vectorized weight staging (2048 float4 per chunk)
        for (int i = tid; i < 2048; i += THREADS_FUSED) {
            int k = i >> 4, n4 = i & 15;
            float4 v = *(const float4*)&g_wqkv[k * 384 + ch * 64 + n4 * 4];
            *(float4*)&Ws[k * WS_STRIDE + n4 * 4] = v;
        }
        __syncthreads();
        float acc[4][4];
        #pragma unroll
        for (int nt = 0; nt < 4; ++nt)
            #pragma unroll
            for (int j = 0; j < 4; ++j) acc[nt][j] = 0.f;
        #pragma unroll
        for (int kk = 0; kk < 16; ++kk) {
            int krow = kk * 8;
            #pragma unroll
            for (int nt = 0; nt < 4; ++nt) {
                int nc = nh * 32 + nt * 8 + g;
                uint32_t b0 = __float_as_uint(Ws[(krow + tq) * WS_STRIDE + nc]);
                uint32_t b1 = __float_as_uint(Ws[(krow + tq + 4) * WS_STRIDE + nc]);
                mma8(acc[nt], a[kk], b0, b1);
            }
        }
        #pragma unroll
        for (int nt = 0; nt < 4; ++nt) {
            int col = ch * 64 + nh * 32 + nt * 8 + 2 * tq;
            float t0 = g_tw[col], t1 = g_tw[col + 1];
            *(float2*)&Qs[r0 * QS_STRIDE + col] =
                make_float2(acc[nt][0] + t0, acc[nt][1] + t1);
            *(float2*)&Qs[(r0 + 8) * QS_STRIDE + col] =
                make_float2(acc[nt][2] + t0, acc[nt][3] + t1);
        }
        __syncthreads();
    }

    // ---- P2: per-(batch,head) masked softmax attention ----
    // Half-warp owns one (b,h) pair; lanes = query rows. K/V row loads are
    // BROADCAST LDS.128 (1 address per half-warp) -> ~10x less crossbar traffic.
    {
        const int half = lane >> 4;
        const int i = lane & 15;
        const bool rowok = (i < VN);
        #pragma unroll
        for (int it = 0; it < 4; ++it) {
            int p = it * 20 + warp * 2 + half;   // (batch_in_block, head) pair id
            bool act = (p < 64);
            int b = act ? (p >> 3) : 0;
            int h = act ? (p & 7) : 0;
            const float* qbase = &Qs[(b * VN) * QS_STRIDE + h * 16];

            // per-lane q row (float4 x4)
            float4 q0, q1, q2, q3;
            {
                const float4* qr = (const float4*)(qbase + (rowok ? i : 0) * QS_STRIDE);
                q0 = qr[0]; q1 = qr[1]; q2 = qr[2]; q3 = qr[3];
            }
            // per-lane mask row
            float mrow[VN];
            #pragma unroll
            for (int j = 0; j < VN; ++j)
                mrow[j] = Mk[(rowok ? i : 0) * VN + j] * 0.25f;

            float e[VN];
            float ssum = 0.f;
            #pragma unroll
            for (int j = 0; j < VN; ++j) {
                // broadcast K[j] (same addr across half-warp)
                const float4* kr = (const float4*)(qbase + j * QS_STRIDE + 128);
                float4 k0 = kr[0], k1 = kr[1], k2 = kr[2], k3 = kr[3];
                float dot =
                    q0.x * k0.x + q0.y * k0.y + q0.z * k0.z + q0.w * k0.w +
                    q1.x * k1.x + q1.y * k1.y + q1.z * k1.z + q1.w * k1.w +
                    q2.x * k2.x + q2.y * k2.y + q2.z * k2.z + q2.w * k2.w +
                    q3.x * k3.x + q3.y * k3.y + q3.z * k3.z + q3.w * k3.w;
                e[j] = __expf(dot * mrow[j]);
                ssum += e[j];
            }
            float4 o0 = {0,0,0,0}, o1 = {0,0,0,0}, o2 = {0,0,0,0}, o3 = {0,0,0,0};
            #pragma unroll
            for (int j = 0; j < VN; ++j) {
                // broadcast V[j]
                const float4* vr = (const float4*)(qbase + j * QS_STRIDE + 256);
                float4 v0 = vr[0], v1 = vr[1], v2 = vr[2], v3 = vr[3];
                float wj = e[j];
                o0.x += wj * v0.x; o0.y += wj * v0.y; o0.z += wj * v0.z; o0.w += wj * v0.w;
                o1.x += wj * v1.x; o1.y += wj * v1.y; o1.z += wj * v1.z; o1.w += wj * v1.w;
                o2.x += wj * v2.x; o2.y += wj * v2.y; o2.z += wj * v2.z; o2.w += wj * v2.w;
                o3.x += wj * v3.x; o3.y += wj * v3.y; o3.z += wj * v3.z; o3.w += wj * v3.w;
            }
            if (act && rowok) {
                float inv = 1.0f / ssum;
                float4 r;
                float* dst = &Xs[(b * VN + i) * XS_STRIDE + h * 16];
                r.x = __uint_as_float(f2tf32(o0.x * inv));
                r.y = __uint_as_float(f2tf32(o0.y * inv));
                r.z = __uint_as_float(f2tf32(o0.z * inv));
                r.w = __uint_as_float(f2tf32(o0.w * inv));
                *(float4*)(dst + 0) = r;
                r.x = __uint_as_float(f2tf32(o1.x * inv));
                r.y = __uint_as_float(f2tf32(o1.y * inv));
                r.z = __uint_as_float(f2tf32(o1.z * inv));
                r.w = __uint_as_float(f2tf32(o1.w * inv));
                *(float4*)(dst + 4) = r;
                r.x = __uint_as_float(f2tf32(o2.x * inv));
                r.y = __uint_as_float(f2tf32(o2.y * inv));
                r.z = __uint_as_float(f2tf32(o2.z * inv));
                r.w = __uint_as_float(f2tf32(o2.w * inv));
                *(float4*)(dst + 8) = r;
                r.x = __uint_as_float(f2tf32(o3.x * inv));
                r.y = __uint_as_float(f2tf32(o3.y * inv));
                r.z = __uint_as_float(f2tf32(o3.z * inv));
                r.w = __uint_as_float(f2tf32(o3.w * inv));
                *(float4*)(dst + 12) = r;
            }
        }
    }
    __syncthreads();

    // ---- P3: out = O @ w_out + b_out ----
    #pragma unroll
    for (int kk = 0; kk < 16; ++kk) {
        int kb = kk * 8;
        a[kk][0] = __float_as_uint(Xs[r0 * XS_STRIDE + kb + tq]);
        a[kk][1] = __float_as_uint(Xs[(r0 + 8) * XS_STRIDE + kb + tq]);
        a[kk][2] = __float_as_uint(Xs[r0 * XS_STRIDE + kb + tq + 4]);
        a[kk][3] = __float_as_uint(Xs[(r0 + 8) * XS_STRIDE + kb + tq + 4]);
    }
    for (int ch = 0; ch < 2; ++ch) {
        for (int i = tid; i < 2048; i += THREADS_FUSED) {
            int k = i >> 4, n4 = i & 15;
            float4 v = *(const float4*)&g_wout[k * 128 + ch * 64 + n4 * 4];
            *(float4*)&Ws[k * WS_STRIDE + n4 * 4] = v;
        }
        __syncthreads();
        float acc[4][4];
        #pragma unroll
        for (int nt = 0; nt < 4; ++nt)
            #pragma unroll
            for (int j = 0; j < 4; ++j) acc[nt][j] = 0.f;
        #pragma unroll
        for (int kk = 0; kk < 16; ++kk) {
            int krow = kk * 8;
            #pragma unroll
            for (int nt = 0; nt < 4; ++nt) {
                int nc = nh * 32 + nt * 8 + g;
                uint32_t b0 = __float_as_uint(Ws[(krow + tq) * WS_STRIDE + nc]);
                uint32_t b1 = __float_as_uint(Ws[(krow + tq + 4) * WS_STRIDE + nc]);
                mma8(acc[nt], a[kk], b0, b1);
            }
        }
        #pragma unroll
        for (int nt = 0; nt < 4; ++nt) {
            int col = ch * 64 + nh * 32 + nt * 8 + 2 * tq;
            float b0v = b_out[col], b1v = b_out[col + 1];
            size_t ro = ((size_t)blk * M_ROWS + r0) * C + col;
            *(float2*)&out[ro] = make_float2(acc[nt][0] + b0v, acc[nt][1] + b1v);
            *(float2*)&out[ro + 8 * C] = make_float2(acc[nt][2] + b0v, acc[nt][3] + b1v);
        }
        __syncthreads();
    }
}

// ================= launch =================
extern "C" void kernel_launch(void* const* d_in, const int* in_sizes, int n_in,
                              void* d_out, int out_size) {
    const float* x     = (const float*)d_in[0];
    const float* gamma = (const float*)d_in[1];
    const float* beta  = (const float*)d_in[2];
    const float* wqkv  = (const float*)d_in[3];
    const float* wout  = (const float*)d_in[4];
    const float* bout  = (const float*)d_in[5];
    const float* mask  = (const float*)d_in[6];

    cudaFuncSetAttribute(k_fused, cudaFuncAttributeMaxDynamicSharedMemorySize, SMEM_BYTES);

    k_stats<<<STATS_BLOCKS, 256>>>((const float4*)x);
    k_prep<<<1, 384>>>(gamma, beta, wqkv, wout);
    k_fused<<<GRID_FUSED, THREADS_FUSED, SMEM_BYTES>>>(x, bout, mask, (float*)d_out);
}

// round 8
// speedup vs baseline: 1.0671x; 1.0099x over previous
#include <cuda_runtime.h>
#include <cstdint>
#include <cstddef>

// ---------------- problem constants ----------------
#define B_TOTAL   32768            // N*T = 64*512
#define VN        10
#define C         128
#define NB        4                // batch items per block
#define M_ROWS    40               // NB*VN
#define GRID_FUSED (B_TOTAL / NB)  // 8192
#define THREADS_FUSED 192          // 6 warps: (mtile 0..2) x (nhalf 0..1)
#define STATS_BLOCKS 1184
#define N4_TOTAL  10485760         // 64*512*10*128/4
#define CNT_INV   (1.0f / 327680.0f)
#define BN_EPS    1e-5f

// ---------------- smem layout (floats) ----------------
#define XS_STRIDE 132
#define QS_STRIDE 388              // divisible by 4 -> float4-aligned rows
#define WS_STRIDE 56               // banks {0,24,16,8}+g -> conflict-free B loads
#define XS_OFF    0
#define QS_OFF    (M_ROWS * XS_STRIDE)                 // 5280
#define WS_OFF    (QS_OFF + M_ROWS * QS_STRIDE)        // + 15520 = 20800
#define MK_OFF    (WS_OFF + 128 * WS_STRIDE)           // + 7168  = 27968
#define SMEM_FLOATS (MK_OFF + 100)                     // 28068
#define SMEM_BYTES  (SMEM_FLOATS * 4)                  // 112272 B -> 2 CTAs/SM

// ---------------- device scratch (no allocation allowed) ----------------
__device__ float g_part[STATS_BLOCKS * 256];   // per-block partial sums / sumsq
__device__ float g_wqkv[128 * 384];            // tf32-rounded s-scaled qkv weights
__device__ float g_tw[384];                    // t @ w_qkv  (fp32 exact)
__device__ float g_wout[128 * 128];            // tf32-rounded output proj weights

// ---------------- helpers ----------------
__device__ __forceinline__ uint32_t f2tf32(float x) {
    uint32_t u;
    asm("cvt.rna.tf32.f32 %0, %1;" : "=r"(u) : "f"(x));
    return u;
}

__device__ __forceinline__ void mma8(float* c, const uint32_t* a, uint32_t b0, uint32_t b1) {
    asm volatile(
        "mma.sync.aligned.m16n8k8.row.col.f32.tf32.tf32.f32 "
        "{%0,%1,%2,%3}, {%4,%5,%6,%7}, {%8,%9}, {%0,%1,%2,%3};\n"
        : "+f"(c[0]), "+f"(c[1]), "+f"(c[2]), "+f"(c[3])
        : "r"(a[0]), "r"(a[1]), "r"(a[2]), "r"(a[3]), "r"(b0), "r"(b1));
}

// ================= kernel 1: BN statistics (deterministic) =================
__global__ void __launch_bounds__(256) k_stats(const float4* __restrict__ x) {
    float sx = 0.f, sy = 0.f, sz = 0.f, sw = 0.f;
    float qx = 0.f, qy = 0.f, qz = 0.f, qw = 0.f;
    const int stride = STATS_BLOCKS * 256;   // multiple of 32 -> fixed channel quad per thread
    for (int i = blockIdx.x * 256 + threadIdx.x; i < N4_TOTAL; i += stride) {
        float4 v = x[i];
        sx += v.x; sy += v.y; sz += v.z; sw += v.w;
        qx += v.x * v.x; qy += v.y * v.y; qz += v.z * v.z; qw += v.w * v.w;
    }
    __shared__ float sh[4096];   // [0:2048) sums, [2048:4096) sumsq; 8 warps x 128ch
    int w = threadIdx.x >> 5, l = threadIdx.x & 31;
    sh[w * 128 + l * 4 + 0] = sx; sh[w * 128 + l * 4 + 1] = sy;
    sh[w * 128 + l * 4 + 2] = sz; sh[w * 128 + l * 4 + 3] = sw;
    sh[2048 + w * 128 + l * 4 + 0] = qx; sh[2048 + w * 128 + l * 4 + 1] = qy;
    sh[2048 + w * 128 + l * 4 + 2] = qz; sh[2048 + w * 128 + l * 4 + 3] = qw;
    __syncthreads();
    int t = threadIdx.x;
    if (t < 128) {
        float a = 0.f;
        #pragma unroll
        for (int ww = 0; ww < 8; ++ww) a += sh[ww * 128 + t];
        g_part[blockIdx.x * 256 + t] = a;
    } else if (t < 256) {
        int u = t - 128;
        float a = 0.f;
        #pragma unroll
        for (int ww = 0; ww < 8; ++ww) a += sh[2048 + ww * 128 + u];
        g_part[blockIdx.x * 256 + t] = a;
    }
}

// ================= kernel 2: fold BN into weights =================
__global__ void __launch_bounds__(384) k_prep(
    const float* __restrict__ gamma, const float* __restrict__ beta,
    const float* __restrict__ wqkv, const float* __restrict__ wout)
{
    __shared__ float s_sum[256];
    __shared__ float s_s[128], s_t[128];
    int t = threadIdx.x;
    if (t < 256) {
        float a = 0.f;
        for (int b = 0; b < STATS_BLOCKS; ++b) a += g_part[b * 256 + t];
        s_sum[t] = a;
    }
    __syncthreads();
    if (t < 128) {
        float mean = s_sum[t] * CNT_INV;
        float var  = s_sum[128 + t] * CNT_INV - mean * mean;
        float rstd = 1.0f / sqrtf(var + BN_EPS);
        float sc = gamma[t] * rstd;
        s_s[t] = sc;
        s_t[t] = beta[t] - mean * sc;
    }
    __syncthreads();
    // W' = diag(s) * w_qkv  (tf32-rounded); t stride = 384 so n = t, k = iter
    for (int k = 0; k < 128; ++k)
        g_wqkv[k * 384 + t] = __uint_as_float(f2tf32(s_s[k] * wqkv[k * 384 + t]));
    // tW = t @ w_qkv (fp32 exact)
    {
        float a = 0.f;
        for (int k = 0; k < 128; ++k) a += s_t[k] * wqkv[k * 384 + t];
        g_tw[t] = a;
    }
    for (int i = t; i < 16384; i += 384)
        g_wout[i] = __uint_as_float(f2tf32(wout[i]));
}

// ================= kernel 3: fused qkv GEMM + attention + out-proj =================
__global__ void __launch_bounds__(THREADS_FUSED, 2) k_fused(
    const float* __restrict__ x, const float* __restrict__ b_out,
    const float* __restrict__ mask, float* __restrict__ out)
{
    extern __shared__ float sm[];
    float* Xs = sm + XS_OFF;   // X tile (tf32), later reused as attention output O
    float* Qs = sm + QS_OFF;   // qkv fp32, 40 x 388
    float* Ws = sm + WS_OFF;   // weight chunk 128 x 56 (48 used)
    float* Mk = sm + MK_OFF;   // 10x10 mask

    const int tid = threadIdx.x;
    const int warp = tid >> 5, lane = tid & 31;
    const int g = lane >> 2, tq = lane & 3;
    const int blk = blockIdx.x;

    // ---- P0: stage X tile (tf32-rounded), fully coalesced ----
    const float4* xg = (const float4*)(x + (size_t)blk * (NB * VN * C));
    for (int idx = tid; idx < 1280; idx += THREADS_FUSED) {   // 40 rows x 32 f4
        int row = idx >> 5, c4 = idx & 31;
        float4 v = xg[idx];
        float4 o;
        o.x = __uint_as_float(f2tf32(v.x));
        o.y = __uint_as_float(f2tf32(v.y));
        o.z = __uint_as_float(f2tf32(v.z));
        o.w = __uint_as_float(f2tf32(v.w));
        *(float4*)&Xs[row * XS_STRIDE + c4 * 4] = o;
    }
    if (tid < 100) Mk[tid] = mask[tid];
    __syncthreads();

    const int mt = warp >> 1;     // m-tile (0..2); tile 2 half-valid (rows 32..39)
    const int nh = warp & 1;      // n-half of the 48-wide chunk
    const int r0 = mt * 16 + g;
    const bool hi_ok = (mt < 2);  // rows r0+8 valid only for tiles 0,1

    // ---- preload A fragments for the whole K=128 into registers ----
    // (tile 2 upper-half rows read OOB into Qs region: harmless garbage, outputs discarded)
    uint32_t a[16][4];
    #pragma unroll
    for (int kk = 0; kk < 16; ++kk) {
        int kb = kk * 8;
        a[kk][0] = __float_as_uint(Xs[r0 * XS_STRIDE + kb + tq]);
        a[kk][1] = __float_as_uint(Xs[(r0 + 8) * XS_STRIDE + kb + tq]);
        a[kk][2] = __float_as_uint(Xs[r0 * XS_STRIDE + kb + tq + 4]);
        a[kk][3] = __float_as_uint(Xs[(r0 + 8) * XS_STRIDE + kb + tq + 4]);
    }

    // ---- P1: qkv = X @ W' + tW, N streamed in 8 chunks of 48 ----
    for (int ch = 0; ch < 8; ++ch) {
        // stage 128x48 weight chunk (1536 float4)
        for (int i = tid; i < 1536; i += THREADS_FUSED) {
            int k = i / 12, n4 = i % 12;
            float4 v = *(const float4*)&g_wqkv[k * 384 + ch * 48 + n4 * 4];
            *(float4*)&Ws[k * WS_STRIDE + n4 * 4] = v;
        }
        __syncthreads();
        float acc[3][4];
        #pragma unroll
        for (int nt = 0; nt < 3; ++nt)
            #pragma unroll
            for (int j = 0; j < 4; ++j) acc[nt][j] = 0.f;
        #pragma unroll
        for (int kk = 0; kk < 16; ++kk) {
            int krow = kk * 8;
            #pragma unroll
            for (int nt = 0; nt < 3; ++nt) {
                int nc = nh * 24 + nt * 8 + g;
                uint32_t b0 = __float_as_uint(Ws[(krow + tq) * WS_STRIDE + nc]);
                uint32_t b1 = __float_as_uint(Ws[(krow + tq + 4) * WS_STRIDE + nc]);
                mma8(acc[nt], a[kk], b0, b1);
            }
        }
        #pragma unroll
        for (int nt = 0; nt < 3; ++nt) {
            int col = ch * 48 + nh * 24 + nt * 8 + 2 * tq;
            float t0 = g_tw[col], t1 = g_tw[col + 1];
            *(float2*)&Qs[r0 * QS_STRIDE + col] =
                make_float2(acc[nt][0] + t0, acc[nt][1] + t1);
            if (hi_ok)
                *(float2*)&Qs[(r0 + 8) * QS_STRIDE + col] =
                    make_float2(acc[nt][2] + t0, acc[nt][3] + t1);
        }
        __syncthreads();
    }

    // ---- P2: per-(batch,head) masked softmax attention ----
    // Half-warp owns one (b,h) pair; lanes = query rows. K/V loads are broadcast LDS.128.
    {
        const int half = lane >> 4;
        const int i = lane & 15;
        const bool rowok = (i < VN);
        #pragma unroll
        for (int it = 0; it < 3; ++it) {
            int p = it * 12 + warp * 2 + half;   // (batch_in_block, head) pair id
            bool act = (p < 32);
            int b = act ? (p >> 3) : 0;
            int h = act ? (p & 7) : 0;
            const float* qbase = &Qs[(b * VN) * QS_STRIDE + h * 16];

            float4 q0, q1, q2, q3;
            {
                const float4* qr = (const float4*)(qbase + (rowok ? i : 0) * QS_STRIDE);
                q0 = qr[0]; q1 = qr[1]; q2 = qr[2]; q3 = qr[3];
            }
            float mrow[VN];
            #pragma unroll
            for (int j = 0; j < VN; ++j)
                mrow[j] = Mk[(rowok ? i : 0) * VN + j] * 0.25f;

            float e[VN];
            float ssum = 0.f;
            #pragma unroll
            for (int j = 0; j < VN; ++j) {
                const float4* kr = (const float4*)(qbase + j * QS_STRIDE + 128);
                float4 k0 = kr[0], k1 = kr[1], k2 = kr[2], k3 = kr[3];
                float dot =
                    q0.x * k0.x + q0.y * k0.y + q0.z * k0.z + q0.w * k0.w +
                    q1.x * k1.x + q1.y * k1.y + q1.z * k1.z + q1.w * k1.w +
                    q2.x * k2.x + q2.y * k2.y + q2.z * k2.z + q2.w * k2.w +
                    q3.x * k3.x + q3.y * k3.y + q3.z * k3.z + q3.w * k3.w;
                e[j] = __expf(dot * mrow[j]);
                ssum += e[j];
            }
            float4 o0 = {0,0,0,0}, o1 = {0,0,0,0}, o2 = {0,0,0,0}, o3 = {0,0,0,0};
            #pragma unroll
            for (int j = 0; j < VN; ++j) {
                const float4* vr = (const float4*)(qbase + j * QS_STRIDE + 256);
                float4 v0 = vr[0], v1 = vr[1], v2 = vr[2], v3 = vr[3];
                float wj = e[j];
                o0.x += wj * v0.x; o0.y += wj * v0.y; o0.z += wj * v0.z; o0.w += wj * v0.w;
                o1.x += wj * v1.x; o1.y += wj * v1.y; o1.z += wj * v1.z; o1.w += wj * v1.w;
                o2.x += wj * v2.x; o2.y += wj * v2.y; o2.z += wj * v2.z; o2.w += wj * v2.w;
                o3.x += wj * v3.x; o3.y += wj * v3.y; o3.z += wj * v3.z; o3.w += wj * v3.w;
            }
            if (act && rowok) {
                float inv = 1.0f / ssum;
                float4 r;
                float* dst = &Xs[(b * VN + i) * XS_STRIDE + h * 16];
                r.x = __uint_as_float(f2tf32(o0.x * inv));
                r.y = __uint_as_float(f2tf32(o0.y * inv));
                r.z = __uint_as_float(f2tf32(o0.z * inv));
                r.w = __uint_as_float(f2tf32(o0.w * inv));
                *(float4*)(dst + 0) = r;
                r.x = __uint_as_float(f2tf32(o1.x * inv));
                r.y = __uint_as_float(f2tf32(o1.y * inv));
                r.z = __uint_as_float(f2tf32(o1.z * inv));
                r.w = __uint_as_float(f2tf32(o1.w * inv));
                *(float4*)(dst + 4) = r;
                r.x = __uint_as_float(f2tf32(o2.x * inv));
                r.y = __uint_as_float(f2tf32(o2.y * inv));
                r.z = __uint_as_float(f2tf32(o2.z * inv));
                r.w = __uint_as_float(f2tf32(o2.w * inv));
                *(float4*)(dst + 8) = r;
                r.x = __uint_as_float(f2tf32(o3.x * inv));
                r.y = __uint_as_float(f2tf32(o3.y * inv));
                r.z = __uint_as_float(f2tf32(o3.z * inv));
                r.w = __uint_as_float(f2tf32(o3.w * inv));
                *(float4*)(dst + 12) = r;
            }
        }
    }
    __syncthreads();

    // ---- P3: out = O @ w_out + b_out, 4 chunks of 32 ----
    #pragma unroll
    for (int kk = 0; kk < 16; ++kk) {
        int kb = kk * 8;
        a[kk][0] = __float_as_uint(Xs[r0 * XS_STRIDE + kb + tq]);
        a[kk][1] = __float_as_uint(Xs[(r0 + 8) * XS_STRIDE + kb + tq]);
        a[kk][2] = __float_as_uint(Xs[r0 * XS_STRIDE + kb + tq + 4]);
        a[kk][3] = __float_as_uint(Xs[(r0 + 8) * XS_STRIDE + kb + tq + 4]);
    }
    for (int ch = 0; ch < 4; ++ch) {
        for (int i = tid; i < 1024; i += THREADS_FUSED) {   // 128 x 8 float4
            int k = i >> 3, n4 = i & 7;
            float4 v = *(const float4*)&g_wout[k * 128 + ch * 32 + n4 * 4];
            *(float4*)&Ws[k * WS_STRIDE + n4 * 4] = v;
        }
        __syncthreads();
        float acc[2][4];
        #pragma unroll
        for (int nt = 0; nt < 2; ++nt)
            #pragma unroll
            for (int j = 0; j < 4; ++j) acc[nt][j] = 0.f;
        #pragma unroll
        for (int kk = 0; kk < 16; ++kk) {
            int krow = kk * 8;
            #pragma unroll
            for (int nt = 0; nt < 2; ++nt) {
                int nc = nh * 16 + nt * 8 + g;
                uint32_t b0 = __float_as_uint(Ws[(krow + tq) * WS_STRIDE + nc]);
                uint32_t b1 = __float_as_uint(Ws[(krow + tq + 4) * WS_STRIDE + nc]);
                mma8(acc[nt], a[kk], b0, b1);
            }
        }
        #pragma unroll
        for (int nt = 0; nt < 2; ++nt) {
            int col = ch * 32 + nh * 16 + nt * 8 + 2 * tq;
            float b0v = b_out[col], b1v = b_out[col + 1];
            size_t ro = ((size_t)blk * M_ROWS + r0) * C + col;
            *(float2*)&out[ro] = make_float2(acc[nt][0] + b0v, acc[nt][1] + b1v);
            if (hi_ok)
                *(float2*)&out[ro + 8 * C] = make_float2(acc[nt][2] + b0v, acc[nt][3] + b1v);
        }
        __syncthreads();
    }
}

// ================= launch =================
extern "C" void kernel_launch(void* const* d_in, const int* in_sizes, int n_in,
                              void* d_out, int out_size) {
    const float* x     = (const float*)d_in[0];
    const float* gamma = (const float*)d_in[1];
    const float* beta  = (const float*)d_in[2];
    const float* wqkv  = (const float*)d_in[3];
    const float* wout  = (const float*)d_in[4];
    const float* bout  = (const float*)d_in[5];
    const float* mask  = (const float*)d_in[6];

    cudaFuncSetAttribute(k_fused, cudaFuncAttributeMaxDynamicSharedMemorySize, SMEM_BYTES);

    k_stats<<<STATS_BLOCKS, 256>>>((const float4*)x);
    k_prep<<<1, 384>>>(gamma, beta, wqkv, wout);
    k_fused<<<GRID_FUSED, THREADS_FUSED, SMEM_BYTES>>>(x, bout, mask, (float*)d_out);
}

// round 10
// speedup vs baseline: 1.8007x; 1.6875x over previous
#include <cuda_runtime.h>
#include <cuda_fp16.h>
#include <cstdint>
#include <cstddef>

// ---------------- problem constants ----------------
#define B_TOTAL   32768            // N*T = 64*512
#define VN        10
#define C         128
#define NB        8                // batch items per block
#define M_ROWS    80               // NB*VN -> 5 exact m16 tiles
#define GRID_FUSED (B_TOTAL / NB)  // 4096
#define THREADS_FUSED 320          // 10 warps: (mtile 0..4) x (nhalf 0..1)
#define STATS_BLOCKS 1184
#define N4_TOTAL  10485760         // 64*512*10*128/4
#define CNT_INV   (1.0f / 327680.0f)
#define BN_EPS    1e-5f

// ---------------- smem layout (bytes; half-precision tiles) ----------------
#define XS_STRH   136              // halfs per X/O row (128 + pad)
#define QS_STRH   392              // halfs per qkv row (384 + pad, 16B-mult)
#define WS_STRH   136              // halfs per transposed-weight row
#define XS_OFF    0                                   // 80*136*2 = 21760
#define QS_OFF    21760                               // 80*392*2 = 62720
#define WS_OFF    84480                               // 64*136*2 = 17408
#define MK_OFF    101888                              // 100*4
#define SMEM_BYTES 102288                             // -> 2 CTAs/SM

// ---------------- device scratch (no allocation allowed) ----------------
__device__ float g_part[STATS_BLOCKS * 256];            // stats partials
__device__ __align__(16) __half g_wqkvT[384 * 128];     // fp16, n-major (s-folded)
__device__ float g_tw[384];                             // t @ w_qkv (fp32 exact)
__device__ __align__(16) __half g_woutT[128 * 128];     // fp16, n-major

// ---------------- helpers ----------------
__device__ __forceinline__ void mma16(float* c, const uint32_t* a, uint32_t b0, uint32_t b1) {
    asm volatile(
        "mma.sync.aligned.m16n8k16.row.col.f32.f16.f16.f32 "
        "{%0,%1,%2,%3}, {%4,%5,%6,%7}, {%8,%9}, {%0,%1,%2,%3};\n"
        : "+f"(c[0]), "+f"(c[1]), "+f"(c[2]), "+f"(c[3])
        : "r"(a[0]), "r"(a[1]), "r"(a[2]), "r"(a[3]), "r"(b0), "r"(b1));
}

__device__ __forceinline__ void h8_to_f(uint4 u, float* f) {
    float2 t;
    t = __half22float2(*(__half2*)&u.x); f[0] = t.x; f[1] = t.y;
    t = __half22float2(*(__half2*)&u.y); f[2] = t.x; f[3] = t.y;
    t = __half22float2(*(__half2*)&u.z); f[4] = t.x; f[5] = t.y;
    t = __half22float2(*(__half2*)&u.w); f[6] = t.x; f[7] = t.y;
}

// ================= kernel 1: BN statistics (deterministic) =================
__global__ void __launch_bounds__(256) k_stats(const float4* __restrict__ x) {
    float sx = 0.f, sy = 0.f, sz = 0.f, sw = 0.f;
    float qx = 0.f, qy = 0.f, qz = 0.f, qw = 0.f;
    const int stride = STATS_BLOCKS * 256;
    for (int i = blockIdx.x * 256 + threadIdx.x; i < N4_TOTAL; i += stride) {
        float4 v = x[i];
        sx += v.x; sy += v.y; sz += v.z; sw += v.w;
        qx += v.x * v.x; qy += v.y * v.y; qz += v.z * v.z; qw += v.w * v.w;
    }
    __shared__ float sh[4096];
    int w = threadIdx.x >> 5, l = threadIdx.x & 31;
    sh[w * 128 + l * 4 + 0] = sx; sh[w * 128 + l * 4 + 1] = sy;
    sh[w * 128 + l * 4 + 2] = sz; sh[w * 128 + l * 4 + 3] = sw;
    sh[2048 + w * 128 + l * 4 + 0] = qx; sh[2048 + w * 128 + l * 4 + 1] = qy;
    sh[2048 + w * 128 + l * 4 + 2] = qz; sh[2048 + w * 128 + l * 4 + 3] = qw;
    __syncthreads();
    int t = threadIdx.x;
    if (t < 128) {
        float a = 0.f;
        #pragma unroll
        for (int ww = 0; ww < 8; ++ww) a += sh[ww * 128 + t];
        g_part[blockIdx.x * 256 + t] = a;
    } else if (t < 256) {
        int u = t - 128;
        float a = 0.f;
        #pragma unroll
        for (int ww = 0; ww < 8; ++ww) a += sh[2048 + ww * 128 + u];
        g_part[blockIdx.x * 256 + t] = a;
    }
}

// ================= kernel 2: fold BN into weights (fp16, transposed) =================
__global__ void __launch_bounds__(384) k_prep(
    const float* __restrict__ gamma, const float* __restrict__ beta,
    const float* __restrict__ wqkv, const float* __restrict__ wout)
{
    __shared__ float s_sum[256];
    __shared__ float s_s[128], s_t[128];
    int t = threadIdx.x;
    if (t < 256) {
        float a = 0.f;
        for (int b = 0; b < STATS_BLOCKS; ++b) a += g_part[b * 256 + t];
        s_sum[t] = a;
    }
    __syncthreads();
    if (t < 128) {
        float mean = s_sum[t] * CNT_INV;
        float var  = s_sum[128 + t] * CNT_INV - mean * mean;
        float rstd = 1.0f / sqrtf(var + BN_EPS);
        float sc = gamma[t] * rstd;
        s_s[t] = sc;
        s_t[t] = beta[t] - mean * sc;
    }
    __syncthreads();
    // W'^T[n][k] = s[k] * w_qkv[k][n]  (fp16)
    for (int k = 0; k < 128; ++k)
        g_wqkvT[t * 128 + k] = __float2half_rn(s_s[k] * wqkv[k * 384 + t]);
    // tW = t @ w_qkv (fp32 exact)
    {
        float a = 0.f;
        for (int k = 0; k < 128; ++k) a += s_t[k] * wqkv[k * 384 + t];
        g_tw[t] = a;
    }
    if (t < 128)
        for (int k = 0; k < 128; ++k)
            g_woutT[t * 128 + k] = __float2half_rn(wout[k * 128 + t]);
}

// ================= kernel 3: fused qkv GEMM + attention + out-proj (fp16 MMA) =================
__global__ void __launch_bounds__(THREADS_FUSED, 2) k_fused(
    const float* __restrict__ x, const float* __restrict__ b_out,
    const float* __restrict__ mask, float* __restrict__ out)
{
    extern __shared__ __align__(16) char smraw[];
    __half* Xs = (__half*)(smraw + XS_OFF);   // X (fp16), later attention output O
    __half* Qs = (__half*)(smraw + QS_OFF);   // qkv fp16, 80 x 392
    __half* Ws = (__half*)(smraw + WS_OFF);   // transposed weight chunk, 64 x 136
    float*  Mk = (float*) (smraw + MK_OFF);   // 10x10 mask

    const int tid = threadIdx.x;
    const int warp = tid >> 5, lane = tid & 31;
    const int g = lane >> 2, tq = lane & 3;
    const int blk = blockIdx.x;

    // ---- P0: stage X tile as fp16, fully coalesced ----
    const float4* xg = (const float4*)(x + (size_t)blk * (NB * VN * C));
    #pragma unroll
    for (int it = 0; it < 8; ++it) {
        int idx = tid + it * THREADS_FUSED;      // 0..2559 exact (80 rows x 32 f4)
        int row = idx >> 5, c4 = idx & 31;
        float4 v = xg[idx];
        __half* dst = &Xs[row * XS_STRH + c4 * 4];
        *(__half2*)(dst + 0) = __floats2half2_rn(v.x, v.y);
        *(__half2*)(dst + 2) = __floats2half2_rn(v.z, v.w);
    }
    if (tid < 100) Mk[tid] = mask[tid];
    __syncthreads();

    const int mt = warp >> 1;     // m-tile (0..4)
    const int nh = warp & 1;      // n-half of the 64-wide chunk
    const int r0 = mt * 16 + g;

    // ---- preload A fragments for K=128 into registers (8 x m16n8k16) ----
    uint32_t a[8][4];
    #pragma unroll
    for (int kk = 0; kk < 8; ++kk) {
        int kb = kk * 16 + 2 * tq;
        a[kk][0] = *(const uint32_t*)&Xs[r0 * XS_STRH + kb];
        a[kk][1] = *(const uint32_t*)&Xs[(r0 + 8) * XS_STRH + kb];
        a[kk][2] = *(const uint32_t*)&Xs[r0 * XS_STRH + kb + 8];
        a[kk][3] = *(const uint32_t*)&Xs[(r0 + 8) * XS_STRH + kb + 8];
    }

    // ---- P1: qkv = X @ W' + tW, N streamed in 6 chunks of 64 ----
    for (int ch = 0; ch < 6; ++ch) {
        // stage 64 n-rows x 128 k halfs (1024 uint4)
        for (int i = tid; i < 1024; i += THREADS_FUSED) {
            int n = i >> 4, q = i & 15;
            uint4 v = ((const uint4*)(g_wqkvT + (ch * 64 + n) * 128))[q];
            ((uint4*)(Ws + n * WS_STRH))[q] = v;
        }
        __syncthreads();
        float acc[4][4];
        #pragma unroll
        for (int nt = 0; nt < 4; ++nt)
            #pragma unroll
            for (int j = 0; j < 4; ++j) acc[nt][j] = 0.f;
        #pragma unroll
        for (int kk = 0; kk < 8; ++kk) {
            int kb = kk * 16 + 2 * tq;
            #pragma unroll
            for (int nt = 0; nt < 4; ++nt) {
                int nc = nh * 32 + nt * 8 + g;
                uint32_t b0 = *(const uint32_t*)&Ws[nc * WS_STRH + kb];
                uint32_t b1 = *(const uint32_t*)&Ws[nc * WS_STRH + kb + 8];
                mma16(acc[nt], a[kk], b0, b1);
            }
        }
        #pragma unroll
        for (int nt = 0; nt < 4; ++nt) {
            int col = ch * 64 + nh * 32 + nt * 8 + 2 * tq;
            float t0 = g_tw[col], t1 = g_tw[col + 1];
            *(__half2*)&Qs[r0 * QS_STRH + col] =
                __floats2half2_rn(acc[nt][0] + t0, acc[nt][1] + t1);
            *(__half2*)&Qs[(r0 + 8) * QS_STRH + col] =
                __floats2half2_rn(acc[nt][2] + t0, acc[nt][3] + t1);
        }
        __syncthreads();
    }

    // ---- P2: per-(batch,head) masked softmax attention ----
    // Half-warp owns one (b,h) pair; lanes = query rows; K/V loads broadcast LDS.128.
    {
        const int half = lane >> 4;
        const int i = lane & 15;
        const bool rowok = (i < VN);
        #pragma unroll
        for (int it = 0; it < 4; ++it) {
            int p = it * 20 + warp * 2 + half;   // (batch_in_block, head) pair id
            bool act = (p < 64);
            int b = act ? (p >> 3) : 0;
            int h = act ? (p & 7) : 0;
            const __half* qbase = &Qs[(b * VN) * QS_STRH + h * 16];

            float q[16];
            {
                const uint4* qr = (const uint4*)(qbase + (rowok ? i : 0) * QS_STRH);
                h8_to_f(qr[0], q);
                h8_to_f(qr[1], q + 8);
            }
            float mrow[VN];
            #pragma unroll
            for (int j = 0; j < VN; ++j)
                mrow[j] = Mk[(rowok ? i : 0) * VN + j] * 0.25f;

            float e[VN];
            float ssum = 0.f;
            #pragma unroll
            for (int j = 0; j < VN; ++j) {
                const uint4* kr = (const uint4*)(qbase + j * QS_STRH + 128);
                float kv[16];
                h8_to_f(kr[0], kv);
                h8_to_f(kr[1], kv + 8);
                float dot = 0.f;
                #pragma unroll
                for (int d = 0; d < 16; ++d) dot += q[d] * kv[d];
                e[j] = __expf(dot * mrow[j]);
                ssum += e[j];
            }
            float o[16];
            #pragma unroll
            for (int d = 0; d < 16; ++d) o[d] = 0.f;
            #pragma unroll
            for (int j = 0; j < VN; ++j) {
                const uint4* vr = (const uint4*)(qbase + j * QS_STRH + 256);
                float vv[16];
                h8_to_f(vr[0], vv);
                h8_to_f(vr[1], vv + 8);
                float wj = e[j];
                #pragma unroll
                for (int d = 0; d < 16; ++d) o[d] += wj * vv[d];
            }
            if (act && rowok) {
                float inv = 1.0f / ssum;
                __half2 hp[8];
                #pragma unroll
                for (int d = 0; d < 8; ++d)
                    hp[d] = __floats2half2_rn(o[2 * d] * inv, o[2 * d + 1] * inv);
                uint4* dst = (uint4*)&Xs[(b * VN + i) * XS_STRH + h * 16];
                dst[0] = *(uint4*)&hp[0];
                dst[1] = *(uint4*)&hp[4];
            }
        }
    }
    __syncthreads();

    // ---- P3: out = O @ w_out + b_out, 2 chunks of 64 ----
    #pragma unroll
    for (int kk = 0; kk < 8; ++kk) {
        int kb = kk * 16 + 2 * tq;
        a[kk][0] = *(const uint32_t*)&Xs[r0 * XS_STRH + kb];
        a[kk][1] = *(const uint32_t*)&Xs[(r0 + 8) * XS_STRH + kb];
        a[kk][2] = *(const uint32_t*)&Xs[r0 * XS_STRH + kb + 8];
        a[kk][3] = *(const uint32_t*)&Xs[(r0 + 8) * XS_STRH + kb + 8];
    }
    for (int ch = 0; ch < 2; ++ch) {
        for (int i = tid; i < 1024; i += THREADS_FUSED) {
            int n = i >> 4, q = i & 15;
            uint4 v = ((const uint4*)(g_woutT + (ch * 64 + n) * 128))[q];
            ((uint4*)(Ws + n * WS_STRH))[q] = v;
        }
        __syncthreads();
        float acc[4][4];
        #pragma unroll
        for (int nt = 0; nt < 4; ++nt)
            #pragma unroll
            for (int j = 0; j < 4; ++j) acc[nt][j] = 0.f;
        #pragma unroll
        for (int kk = 0; kk < 8; ++kk) {
            int kb = kk * 16 + 2 * tq;
            #pragma unroll
            for (int nt = 0; nt < 4; ++nt) {
                int nc = nh * 32 + nt * 8 + g;
                uint32_t b0 = *(const uint32_t*)&Ws[nc * WS_STRH + kb];
                uint32_t b1 = *(const uint32_t*)&Ws[nc * WS_STRH + kb + 8];
                mma16(acc[nt], a[kk], b0, b1);
            }
        }
        #pragma unroll
        for (int nt = 0; nt < 4; ++nt) {
            int col = ch * 64 + nh * 32 + nt * 8 + 2 * tq;
            float b0v = b_out[col], b1v = b_out[col + 1];
            size_t ro = ((size_t)blk * M_ROWS + r0) * C + col;
            *(float2*)&out[ro] = make_float2(acc[nt][0] + b0v, acc[nt][1] + b1v);
            *(float2*)&out[ro + 8 * C] = make_float2(acc[nt][2] + b0v, acc[nt][3] + b1v);
        }
        __syncthreads();
    }
}

// ================= launch =================
extern "C" void kernel_launch(void* const* d_in, const int* in_sizes, int n_in,
                              void* d_out, int out_size) {
    const float* x     = (const float*)d_in[0];
    const float* gamma = (const float*)d_in[1];
    const float* beta  = (const float*)d_in[2];
    const float* wqkv  = (const float*)d_in[3];
    const float* wout  = (const float*)d_in[4];
    const float* bout  = (const float*)d_in[5];
    const float* mask  = (const float*)d_in[6];

    cudaFuncSetAttribute(k_fused, cudaFuncAttributeMaxDynamicSharedMemorySize, SMEM_BYTES);

    k_stats<<<STATS_BLOCKS, 256>>>((const float4*)x);
    k_prep<<<1, 384>>>(gamma, beta, wqkv, wout);
    k_fused<<<GRID_FUSED, THREADS_FUSED, SMEM_BYTES>>>(x, bout, mask, (float*)d_out);
}

// round 12
// speedup vs baseline: 2.4262x; 1.3474x over previous
#include <cuda_runtime.h>
#include <cuda_fp16.h>
#include <cstdint>
#include <cstddef>

// ---------------- problem constants ----------------
#define B_TOTAL   32768
#define VN        10
#define C         128
#define NB        8
#define M_ROWS    80
#define GRID_FUSED 4096
#define THREADS_FUSED 320          // 10 warps: (mtile 0..4) x (nhalf 0..1)
#define STATS_BLOCKS 1184
#define N4_TOTAL  10485760
#define CNT_INV   (1.0f / 327680.0f)
#define BN_EPS    1e-5f

// ---------------- smem layout ----------------
#define XS_STRH   136              // halfs per X/O row
#define QS_STRH   392              // halfs per qkv row
#define WS_STRH   136              // halfs per weight n-row
#define XS_OFF    0                // 80*136*2 = 21760
#define QS_OFF    21760            // 80*392*2 = 62720
#define WS_OFF    84480            // 64*136*2 = 17408
#define MK_OFF    101888           // 100*4
#define SMEM_BYTES 102288          // x2 CTAs/SM

// ---------------- device scratch ----------------
__device__ float g_part[STATS_BLOCKS * 256];
__device__ __align__(16) __half g_wqkvT[384 * 128];   // n-major, s-folded
__device__ float g_tw[384];
__device__ __align__(16) __half g_woutT[128 * 128];   // n-major

// ---------------- helpers ----------------
__device__ __forceinline__ uint32_t smem_u32(const void* p) {
    uint32_t a;
    asm("{ .reg .u64 t; cvta.to.shared.u64 t, %1; cvt.u32.u64 %0, t; }" : "=r"(a) : "l"(p));
    return a;
}
__device__ __forceinline__ void mma16(float* c, const uint32_t* a, uint32_t b0, uint32_t b1) {
    asm volatile(
        "mma.sync.aligned.m16n8k16.row.col.f32.f16.f16.f32 "
        "{%0,%1,%2,%3}, {%4,%5,%6,%7}, {%8,%9}, {%0,%1,%2,%3};\n"
        : "+f"(c[0]), "+f"(c[1]), "+f"(c[2]), "+f"(c[3])
        : "r"(a[0]), "r"(a[1]), "r"(a[2]), "r"(a[3]), "r"(b0), "r"(b1));
}
#define LDSM4(r, addr) \
    asm volatile("ldmatrix.sync.aligned.m8n8.x4.shared.b16 {%0,%1,%2,%3}, [%4];" \
                 : "=r"((r)[0]), "=r"((r)[1]), "=r"((r)[2]), "=r"((r)[3]) : "r"(addr))

__device__ __forceinline__ void h8_to_f(uint4 u, float* f) {
    float2 t;
    t = __half22float2(*(__half2*)&u.x); f[0] = t.x; f[1] = t.y;
    t = __half22float2(*(__half2*)&u.y); f[2] = t.x; f[3] = t.y;
    t = __half22float2(*(__half2*)&u.z); f[4] = t.x; f[5] = t.y;
    t = __half22float2(*(__half2*)&u.w); f[6] = t.x; f[7] = t.y;
}

// ================= kernel 1: BN statistics (deterministic, 2-way MLP) =================
__global__ void __launch_bounds__(256) k_stats(const float4* __restrict__ x) {
    float sx = 0.f, sy = 0.f, sz = 0.f, sw = 0.f;
    float qx = 0.f, qy = 0.f, qz = 0.f, qw = 0.f;
    const int stride = STATS_BLOCKS * 256;   // mult of 32 -> fixed channel quad
    int i = blockIdx.x * 256 + threadIdx.x;
    for (; i + stride < N4_TOTAL; i += 2 * stride) {
        float4 v = x[i];
        float4 u = x[i + stride];
        sx += v.x + u.x; sy += v.y + u.y; sz += v.z + u.z; sw += v.w + u.w;
        qx += v.x * v.x + u.x * u.x; qy += v.y * v.y + u.y * u.y;
        qz += v.z * v.z + u.z * u.z; qw += v.w * v.w + u.w * u.w;
    }
    if (i < N4_TOTAL) {
        float4 v = x[i];
        sx += v.x; sy += v.y; sz += v.z; sw += v.w;
        qx += v.x * v.x; qy += v.y * v.y; qz += v.z * v.z; qw += v.w * v.w;
    }
    __shared__ float sh[4096];
    int w = threadIdx.x >> 5, l = threadIdx.x & 31;
    sh[w * 128 + l * 4 + 0] = sx; sh[w * 128 + l * 4 + 1] = sy;
    sh[w * 128 + l * 4 + 2] = sz; sh[w * 128 + l * 4 + 3] = sw;
    sh[2048 + w * 128 + l * 4 + 0] = qx; sh[2048 + w * 128 + l * 4 + 1] = qy;
    sh[2048 + w * 128 + l * 4 + 2] = qz; sh[2048 + w * 128 + l * 4 + 3] = qw;
    __syncthreads();
    int t = threadIdx.x;
    if (t < 128) {
        float a = 0.f;
        #pragma unroll
        for (int ww = 0; ww < 8; ++ww) a += sh[ww * 128 + t];
        g_part[blockIdx.x * 256 + t] = a;
    } else if (t < 256) {
        int u = t - 128;
        float a = 0.f;
        #pragma unroll
        for (int ww = 0; ww < 8; ++ww) a += sh[2048 + ww * 128 + u];
        g_part[blockIdx.x * 256 + t] = a;
    }
}

// ================= kernel 2: fold BN into weights (fp16, n-major) =================
__global__ void __launch_bounds__(384) k_prep(
    const float* __restrict__ gamma, const float* __restrict__ beta,
    const float* __restrict__ wqkv, const float* __restrict__ wout)
{
    __shared__ float s_sum[256];
    __shared__ float s_s[128], s_t[128];
    int t = threadIdx.x;
    if (t < 256) {
        float a = 0.f;
        for (int b = 0; b < STATS_BLOCKS; ++b) a += g_part[b * 256 + t];
        s_sum[t] = a;
    }
    __syncthreads();
    if (t < 128) {
        float mean = s_sum[t] * CNT_INV;
        float var  = s_sum[128 + t] * CNT_INV - mean * mean;
        float rstd = 1.0f / sqrtf(var + BN_EPS);
        float sc = gamma[t] * rstd;
        s_s[t] = sc;
        s_t[t] = beta[t] - mean * sc;
    }
    __syncthreads();
    for (int k = 0; k < 128; ++k)
        g_wqkvT[t * 128 + k] = __float2half_rn(s_s[k] * wqkv[k * 384 + t]);
    {
        float a = 0.f;
        for (int k = 0; k < 128; ++k) a += s_t[k] * wqkv[k * 384 + t];
        g_tw[t] = a;
    }
    if (t < 128)
        for (int k = 0; k < 128; ++k)
            g_woutT[t * 128 + k] = __float2half_rn(wout[k * 128 + t]);
}

// ================= kernel 3: fused (HMMA + ldmatrix + prefetch + HFMA2 softmax) =================
__global__ void __launch_bounds__(THREADS_FUSED, 2) k_fused(
    const float* __restrict__ x, const float* __restrict__ b_out,
    const float* __restrict__ mask, float* __restrict__ out)
{
    extern __shared__ __align__(16) char smraw[];
    __half* Xs = (__half*)(smraw + XS_OFF);
    __half* Qs = (__half*)(smraw + QS_OFF);
    __half* Ws = (__half*)(smraw + WS_OFF);
    float*  Mk = (float*)(smraw + MK_OFF);
    const uint32_t sbase = smem_u32(smraw);

    const int tid = threadIdx.x;
    const int warp = tid >> 5, lane = tid & 31;
    const int g = lane >> 2, tq = lane & 3;
    const int blk = blockIdx.x;

    const int mt = warp >> 1;     // m-tile (0..4)
    const int nh = warp & 1;      // n-half of the 64-wide chunk
    const int r0 = mt * 16 + g;

    // ldmatrix lane bases (byte smem addresses)
    const int lm = lane >> 3, lr = lane & 7;
    // A: matrix m: row_off=(m&1)*8, k_off=(m>>1)*8
    const uint32_t a_base = sbase + XS_OFF +
        (uint32_t)(((mt * 16 + (lm & 1) * 8 + lr) * XS_STRH + (lm >> 1) * 8) * 2);
    // B: matrix m: n_off=(m>>1)*8, k_off=(m&1)*8 ; two nt-pairs
    uint32_t b_base[2];
    #pragma unroll
    for (int ntp = 0; ntp < 2; ++ntp)
        b_base[ntp] = sbase + WS_OFF +
            (uint32_t)(((nh * 32 + ntp * 16 + (lm >> 1) * 8 + lr) * WS_STRH + (lm & 1) * 8) * 2);

    // ---- P0: stage X tile (fp16) + wqkv chunk0 + mask ----
    const float4* xg = (const float4*)(x + (size_t)blk * (NB * VN * C));
    #pragma unroll
    for (int it = 0; it < 8; ++it) {
        int idx = tid + it * THREADS_FUSED;      // 0..2559 (80 rows x 32 f4)
        int row = idx >> 5, c4 = idx & 31;
        float4 v = xg[idx];
        __half* dst = &Xs[row * XS_STRH + c4 * 4];
        *(__half2*)(dst + 0) = __floats2half2_rn(v.x, v.y);
        *(__half2*)(dst + 2) = __floats2half2_rn(v.z, v.w);
    }
    for (int u = tid; u < 1024; u += THREADS_FUSED) {
        int n = u >> 4, q = u & 15;
        ((uint4*)(Ws + n * WS_STRH))[q] = ((const uint4*)g_wqkvT)[u];
    }
    if (tid < 100) Mk[tid] = mask[tid];
    __syncthreads();

    // ---- preload A fragments via ldmatrix (8 x K16) ----
    uint32_t a[8][4];
    #pragma unroll
    for (int kk = 0; kk < 8; ++kk) LDSM4(a[kk], a_base + kk * 32);

    // ---- P1: qkv in 6 N-chunks of 64, register-prefetched weights ----
    for (int ch = 0; ch < 6; ++ch) {
        uint4 pf[4];
        const bool doPf = (ch < 5) && (tid < 256);
        if (doPf) {
            const uint4* wsrc = (const uint4*)(g_wqkvT + (ch + 1) * 64 * 128);
            #pragma unroll
            for (int j = 0; j < 4; ++j) pf[j] = wsrc[j * 256 + tid];
        }
        float acc[4][4];
        #pragma unroll
        for (int nt = 0; nt < 4; ++nt)
            #pragma unroll
            for (int j = 0; j < 4; ++j) acc[nt][j] = 0.f;
        #pragma unroll
        for (int kk = 0; kk < 8; ++kk) {
            #pragma unroll
            for (int ntp = 0; ntp < 2; ++ntp) {
                uint32_t bb[4];
                LDSM4(bb, b_base[ntp] + kk * 32);
                mma16(acc[ntp * 2 + 0], a[kk], bb[0], bb[1]);
                mma16(acc[ntp * 2 + 1], a[kk], bb[2], bb[3]);
            }
        }
        #pragma unroll
        for (int nt = 0; nt < 4; ++nt) {
            int col = ch * 64 + nh * 32 + nt * 8 + 2 * tq;
            float t0 = g_tw[col], t1 = g_tw[col + 1];
            *(__half2*)&Qs[r0 * QS_STRH + col] =
                __floats2half2_rn(acc[nt][0] + t0, acc[nt][1] + t1);
            *(__half2*)&Qs[(r0 + 8) * QS_STRH + col] =
                __floats2half2_rn(acc[nt][2] + t0, acc[nt][3] + t1);
        }
        __syncthreads();
        if (ch < 5) {
            if (doPf) {
                #pragma unroll
                for (int j = 0; j < 4; ++j) {
                    int u = j * 256 + tid;
                    int n = u >> 4, q = u & 15;
                    ((uint4*)(Ws + n * WS_STRH))[q] = pf[j];
                }
            }
            __syncthreads();
        }
    }

    // ---- stage wout chunk0 into Ws (overlaps with softmax warps) ----
    if (tid < 256) {
        uint4 pf0[4];
        #pragma unroll
        for (int j = 0; j < 4; ++j) pf0[j] = ((const uint4*)g_woutT)[j * 256 + tid];
        #pragma unroll
        for (int j = 0; j < 4; ++j) {
            int u = j * 256 + tid;
            int n = u >> 4, q = u & 15;
            ((uint4*)(Ws + n * WS_STRH))[q] = pf0[j];
        }
    }

    // ---- P2: per-(batch,head) masked softmax; HFMA2 dots; O -> Xs fp16 ----
    {
        const int half = lane >> 4;
        const int i = lane & 15;
        const bool rowok = (i < VN);
        #pragma unroll
        for (int it = 0; it < 4; ++it) {
            int p = it * 20 + warp * 2 + half;
            bool act = (p < 64);
            int b = act ? (p >> 3) : 0;
            int h = act ? (p & 7) : 0;
            const __half* qbase = &Qs[(b * VN) * QS_STRH + h * 16];

            uint4 qv0, qv1;
            {
                const uint4* qr = (const uint4*)(qbase + (rowok ? i : 0) * QS_STRH);
                qv0 = qr[0]; qv1 = qr[1];
            }
            const __half2* qh0 = (const __half2*)&qv0;
            const __half2* qh1 = (const __half2*)&qv1;
            float mrow[VN];
            #pragma unroll
            for (int j = 0; j < VN; ++j)
                mrow[j] = Mk[(rowok ? i : 0) * VN + j] * 0.25f;

            float e[VN];
            float ssum = 0.f;
            #pragma unroll
            for (int j = 0; j < VN; ++j) {
                const uint4* kr = (const uint4*)(qbase + j * QS_STRH + 128);
                uint4 kv0 = kr[0], kv1 = kr[1];
                const __half2* kh0 = (const __half2*)&kv0;
                const __half2* kh1 = (const __half2*)&kv1;
                __half2 s = __hmul2(qh0[0], kh0[0]);
                s = __hfma2(qh0[1], kh0[1], s);
                s = __hfma2(qh0[2], kh0[2], s);
                s = __hfma2(qh0[3], kh0[3], s);
                s = __hfma2(qh1[0], kh1[0], s);
                s = __hfma2(qh1[1], kh1[1], s);
                s = __hfma2(qh1[2], kh1[2], s);
                s = __hfma2(qh1[3], kh1[3], s);
                float2 f = __half22float2(s);
                e[j] = __expf((f.x + f.y) * mrow[j]);
                ssum += e[j];
            }
            float o[16];
            #pragma unroll
            for (int d = 0; d < 16; ++d) o[d] = 0.f;
            #pragma unroll
            for (int j = 0; j < VN; ++j) {
                const uint4* vr = (const uint4*)(qbase + j * QS_STRH + 256);
                float vv[16];
                h8_to_f(vr[0], vv);
                h8_to_f(vr[1], vv + 8);
                float wj = e[j];
                #pragma unroll
                for (int d = 0; d < 16; ++d) o[d] += wj * vv[d];
            }
            if (act && rowok) {
                float inv = 1.0f / ssum;
                __half2 hp[8];
                #pragma unroll
                for (int d = 0; d < 8; ++d)
                    hp[d] = __floats2half2_rn(o[2 * d] * inv, o[2 * d + 1] * inv);
                uint4* dst = (uint4*)&Xs[(b * VN + i) * XS_STRH + h * 16];
                dst[0] = *(uint4*)&hp[0];
                dst[1] = *(uint4*)&hp[4];
            }
        }
    }
    __syncthreads();   // O ready in Xs AND wout chunk0 staged

    // ---- P3: out = O @ w_out + b_out, 2 N-chunks of 64 ----
    #pragma unroll
    for (int kk = 0; kk < 8; ++kk) LDSM4(a[kk], a_base + kk * 32);

    for (int ch = 0; ch < 2; ++ch) {
        uint4 pf[4];
        const bool doPf = (ch == 0) && (tid < 256);
        if (doPf) {
            const uint4* wsrc = (const uint4*)(g_woutT + 64 * 128);
            #pragma unroll
            for (int j = 0; j < 4; ++j) pf[j] = wsrc[j * 256 + tid];
        }
        float acc[4][4];
        #pragma unroll
        for (int nt = 0; nt < 4; ++nt)
            #pragma unroll
            for (int j = 0; j < 4; ++j) acc[nt][j] = 0.f;
        #pragma unroll
        for (int kk = 0; kk < 8; ++kk) {
            #pragma unroll
            for (int ntp = 0; ntp < 2; ++ntp) {
                uint32_t bb[4];
                LDSM4(bb, b_base[ntp] + kk * 32);
                mma16(acc[ntp * 2 + 0], a[kk], bb[0], bb[1]);
                mma16(acc[ntp * 2 + 1], a[kk], bb[2], bb[3]);
            }
        }
        #pragma unroll
        for (int nt = 0; nt < 4; ++nt) {
            int col = ch * 64 + nh * 32 + nt * 8 + 2 * tq;
            float b0v = b_out[col], b1v = b_out[col + 1];
            size_t ro = ((size_t)blk * M_ROWS + r0) * C + col;
            *(float2*)&out[ro] = make_float2(acc[nt][0] + b0v, acc[nt][1] + b1v);
            *(float2*)&out[ro + 8 * C] = make_float2(acc[nt][2] + b0v, acc[nt][3] + b1v);
        }
        if (ch == 0) {
            __syncthreads();
            if (doPf) {
                #pragma unroll
                for (int j = 0; j < 4; ++j) {
                    int u = j * 256 + tid;
                    int n = u >> 4, q = u & 15;
                    ((uint4*)(Ws + n * WS_STRH))[q] = pf[j];
                }
            }
            __syncthreads();
        }
    }
}

// ================= launch =================
extern "C" void kernel_launch(void* const* d_in, const int* in_sizes, int n_in,
                              void* d_out, int out_size) {
    const float* x     = (const float*)d_in[0];
    const float* gamma = (const float*)d_in[1];
    const float* beta  = (const float*)d_in[2];
    const float* wqkv  = (const float*)d_in[3];
    const float* wout  = (const float*)d_in[4];
    const float* bout  = (const float*)d_in[5];
    const float* mask  = (const float*)d_in[6];

    cudaFuncSetAttribute(k_fused, cudaFuncAttributeMaxDynamicSharedMemorySize, SMEM_BYTES);

    k_stats<<<STATS_BLOCKS, 256>>>((const float4*)x);
    k_prep<<<1, 384>>>(gamma, beta, wqkv, wout);
    k_fused<<<GRID_FUSED, THREADS_FUSED, SMEM_BYTES>>>(x, bout, mask, (float*)d_out);
}